// round 4
// baseline (speedup 1.0000x reference)
#include <cuda_runtime.h>
#include <math.h>

#define CCH  32
#define HF   256
#define WF   256
#define MAXW 128
#define MBOX 1024
#define IMG_WORDS (32u * 65536u)           // words per image (C*H*W)

// 134 MB transposed feature map scratch: layout (N, H, W, C), C contiguous.
__device__ float g_fmt[16u * IMG_WORDS];

__device__ float g_p1x[MBOX], g_p1y[MBOX];
__device__ float g_axx[MBOX], g_axy[MBOX];
__device__ float g_ayx[MBOX], g_ayy[MBOX];
__device__ int   g_width[MBOX];
__device__ int   g_rank[MBOX];    // box -> output slot (stable desc width rank)
__device__ int   g_sched[MBOX];   // processing order: boxes grouped by image

// ---------------------------------------------------------------------------
// Kernel 1: transpose (N,C,H,W) -> (N,H,W,C).  Block = 64 spatial px x 32 ch.
// ---------------------------------------------------------------------------
__global__ __launch_bounds__(256) void transpose_kernel(const float* __restrict__ fm)
{
    __shared__ float tile[32][65];
    const int tid  = threadIdx.x;
    const int lane = tid & 31;
    const int wrp  = tid >> 5;

    const int px0 = blockIdx.x << 6;          // 64 px per block (linear over N*H*W)
    const int n   = px0 >> 16;
    const int pxi = px0 & 65535;
    const size_t ibase = (size_t)n * IMG_WORDS;

    // read: coalesced along W, evict-first (read-once)
    #pragma unroll
    for (int t = 0; t < 4; t++) {
        const int cc = wrp + t * 8;
        const float* src = fm + ibase + ((size_t)cc << 16) + pxi;
        tile[cc][lane]      = __ldcs(src + lane);
        tile[cc][lane + 32] = __ldcs(src + lane + 32);
    }
    __syncthreads();

    // write: coalesced along C
    float* dst = g_fmt + ibase + ((size_t)pxi << 5) + lane;
    #pragma unroll
    for (int t = 0; t < 8; t++) {
        const int xo = wrp + t * 8;
        dst[(size_t)xo << 5] = tile[lane][xo];
    }
}

// ---------------------------------------------------------------------------
// Kernel 2: widths (bit-identical discrete math), stable desc-width rank,
// stable by-image rank (scheduling), and per-box sampling geometry.
// ---------------------------------------------------------------------------
__global__ __launch_bounds__(256) void width_rank_kernel(
    const float* __restrict__ boxes, const int* __restrict__ mapping,
    float* __restrict__ out_tail, int M, int write_tail)
{
    __shared__ int sw[MBOX];
    __shared__ int sm[MBOX];
    const int tid = threadIdx.x;

    for (int i = tid; i < MBOX; i += 256) {
        int w = -1, mp = 0x7fffffff;
        if (i < M) {
            const float* b = boxes + i * 8;
            float p1x = b[0]*0.25f, p1y = b[1]*0.25f;
            float p2x = b[2]*0.25f, p2y = b[3]*0.25f;
            float p4x = b[6]*0.25f, p4y = b[7]*0.25f;
            float dx2 = __fadd_rn(p2x,-p1x), dy2 = __fadd_rn(p2y,-p1y);
            float dx4 = __fadd_rn(p4x,-p1x), dy4 = __fadd_rn(p4y,-p1y);
            float bw = __fsqrt_rn(__fadd_rn(__fmul_rn(dx2,dx2), __fmul_rn(dy2,dy2)));
            float bh = __fsqrt_rn(__fadd_rn(__fmul_rn(dx4,dx4), __fmul_rn(dy4,dy4)));
            float bmaj = bw, bmin = bh;
            if (bw <= bh) { bmaj = bh; bmin = bw; }
            float ratio = __fdiv_rn(__fmul_rn(8.0f, bmaj), fmaxf(bmin, 1e-6f));
            w  = (int)fminf(fmaxf(ceilf(ratio), 1.0f), 128.0f);
            mp = mapping[i];
        }
        sw[i] = w;
        sm[i] = mp;
    }
    __syncthreads();

    const int lane = tid & 31, wrp = tid >> 5;
    const int i = blockIdx.x * 8 + wrp;
    if (i < M) {
        const int w  = sw[i];
        const int mp = sm[i];
        int rank = 0, irk = 0;
        #pragma unroll 4
        for (int t = 0; t < MBOX / 32; t++) {
            int j  = t * 32 + lane;
            int wj = sw[j];
            int mj = sm[j];
            rank += (wj > w)  | ((wj == w) & (j < i));
            irk  += (mj < mp) | ((mj == mp) & (j < i));
        }
        #pragma unroll
        for (int o = 16; o; o >>= 1) {
            rank += __shfl_xor_sync(0xffffffffu, rank, o);
            irk  += __shfl_xor_sync(0xffffffffu, irk,  o);
        }
        if (lane == 0) {
            g_rank[i]    = rank;
            g_sched[irk] = i;
            g_width[i]   = w;
            // geometry
            const float* b = boxes + i * 8;
            float p1x = b[0]*0.25f, p1y = b[1]*0.25f;
            float p2x = b[2]*0.25f, p2y = b[3]*0.25f;
            float p4x = b[6]*0.25f, p4y = b[7]*0.25f;
            float dx2 = __fadd_rn(p2x,-p1x), dy2 = __fadd_rn(p2y,-p1y);
            float dx4 = __fadd_rn(p4x,-p1x), dy4 = __fadd_rn(p4y,-p1y);
            float wf = (float)w;
            g_p1x[i] = p1x; g_p1y[i] = p1y;
            g_axx[i] = __fdiv_rn(dx2, wf);
            g_axy[i] = __fdiv_rn(dy2, wf);
            g_ayx[i] = dx4 * 0.125f;
            g_ayy[i] = dy4 * 0.125f;
            if (write_tail) {
                out_tail[rank]     = (float)w;
                out_tail[M + rank] = (float)i;
            }
        }
    }
}

// ---------------------------------------------------------------------------
// Kernel 3: sampler on transposed layout.  Blocks walk boxes grouped by
// image (g_sched) for L2 reuse; each box writes to its sorted slot g_rank.
// Warp = 8 consecutive x of one (box, row y); lane = channel.  Each tap is
// ONE 128B line; output stores streamed (__stcs).
// ---------------------------------------------------------------------------
__global__ __launch_bounds__(256) void sample_kernel(
    const int*   __restrict__ mapping,
    float*       __restrict__ out)
{
    const int tid  = threadIdx.x;
    const int lane = tid & 31;
    const int wrp  = tid >> 5;
    const int bid  = blockIdx.x;

    const int box   = g_sched[bid >> 4];      // 16 blocks per box
    const int k     = g_rank[box];
    const int width = g_width[box];

    const int local = (((bid & 15) << 3) + wrp) << 3;  // 0..1016, step 8
    const int y  = local >> 7;
    const int xs = local & 127;

    const int s0 = (k << 10) + local;                  // global sample index
    float* const op = out + ((size_t)s0 << 5) + lane;  // out linear = s*32 + c

    if (xs >= width) {
        #pragma unroll
        for (int i = 0; i < 8; i++) __stcs(op + ((size_t)i << 5), 0.f);
        return;
    }

    const int n = mapping[box];
    const float* const fb = g_fmt + ((size_t)n * IMG_WORDS) + lane;

    // per-lane geometry for sample i = lane & 7
    const float fx = (float)(xs + (lane & 7));
    const float fy = (float)y;
    const float sx = g_p1x[box] + g_axx[box] * fx + g_ayx[box] * fy;
    const float sy = g_p1y[box] + g_axy[box] * fx + g_ayy[box] * fy;
    const float x0f = floorf(sx), y0f = floorf(sy);
    const float tx = sx - x0f, ty = sy - y0f;
    const int x0 = (int)x0f, y0 = (int)y0f;
    const bool vx0 = ((unsigned)x0       < (unsigned)WF);
    const bool vx1 = ((unsigned)(x0 + 1) < (unsigned)WF);
    const bool vy0 = ((unsigned)y0       < (unsigned)HF);
    const bool vy1 = ((unsigned)(y0 + 1) < (unsigned)HF);
    float w00 = (1.f - tx) * (1.f - ty); if (!(vx0 & vy0)) w00 = 0.f;
    float w01 = tx * (1.f - ty);         if (!(vx1 & vy0)) w01 = 0.f;
    float w10 = (1.f - tx) * ty;         if (!(vx0 & vy1)) w10 = 0.f;
    float w11 = tx * ty;                 if (!(vx1 & vy1)) w11 = 0.f;
    const int xc0 = min(max(x0, 0), WF - 1);
    const int xc1 = min(max(x0 + 1, 0), WF - 1);
    const int yc0 = min(max(y0, 0), HF - 1);
    const int yc1 = min(max(y0 + 1, 0), HF - 1);
    const int o00 = (yc0 << 13) + (xc0 << 5);     // (yc0*256 + xc0)*32
    const int dxo = (xc1 - xc0) << 5;             // 0 or 32
    const int dyo = (yc1 - yc0) << 13;            // 0 or 8192

    #pragma unroll
    for (int i = 0; i < 8; i++) {
        const float W00 = __shfl_sync(0xffffffffu, w00, i);
        const float W01 = __shfl_sync(0xffffffffu, w01, i);
        const float W10 = __shfl_sync(0xffffffffu, w10, i);
        const float W11 = __shfl_sync(0xffffffffu, w11, i);
        const int   O00 = __shfl_sync(0xffffffffu, o00, i);
        const int   DX  = __shfl_sync(0xffffffffu, dxo, i);
        const int   DY  = __shfl_sync(0xffffffffu, dyo, i);
        float v = 0.f;
        if (xs + i < width) {
            const float* p = fb + O00;
            v = W00 * __ldg(p)
              + W01 * __ldg(p + DX)
              + W10 * __ldg(p + DY)
              + W11 * __ldg(p + DX + DY);
        }
        __stcs(op + ((size_t)i << 5), v);
    }
}

// ---------------------------------------------------------------------------
extern "C" void kernel_launch(void* const* d_in, const int* in_sizes, int n_in,
                              void* d_out, int out_size) {
    const float* fm      = (const float*)d_in[0];
    const float* boxes   = (const float*)d_in[1];
    const int*   mapping = (const int*)  d_in[2];
    float*       out     = (float*)d_out;

    const int M = in_sizes[1] / 8;  // 1024
    const size_t main_elems = (size_t)M * 8 * MAXW * CCH;
    const int write_tail = ((size_t)out_size >= main_elems + 2 * (size_t)M) ? 1 : 0;

    const int fm_elems = in_sizes[0];                 // N*C*H*W
    const int tr_blocks = fm_elems / (CCH * 64);      // 64 px per block

    width_rank_kernel<<<(M + 7) / 8, 256>>>(boxes, mapping, out + main_elems, M, write_tail);
    transpose_kernel<<<tr_blocks, 256>>>(fm);
    sample_kernel<<<M * 16, 256>>>(mapping, out);
}